// round 17
// baseline (speedup 1.0000x reference)
#include <cuda_runtime.h>
#include <math.h>

// ---------------- scratch arena (no allocation allowed) ----------------
__device__ float g_act[136600576];
__device__ float g_mean[2048];
__device__ float g_rstd[2048];
__device__ double g_s1[6144];   // per-layer stat accumulators (finalize zeroes after read)
__device__ double g_s2[6144];
__device__ float g_psum[8 * 32 * 3];
__device__ float g_pcnt[8 * 32];

// ---------------- 7x7 reflect conv, 3 -> 16, 512x512, writes padded (raw) + stats ----------------
// block(16,16): out tile 16x32, thread = 2 rows x 16 cout
__global__ __launch_bounds__(256) void k_conv_in(const float* __restrict__ x,
                                                 const float* __restrict__ w,
                                                 const float* __restrict__ bias,
                                                 float* __restrict__ out,
                                                 double* __restrict__ s1,
                                                 double* __restrict__ s2) {
    __shared__ __align__(16) float ws[2352];   // [ci3][k49][co16]
    __shared__ float tile[3 * 38 * 24];        // stride 24 (2*24 % 32 == 16)
    __shared__ float sh_s[128], sh_q[128];
    const int tx = threadIdx.x, ty = threadIdx.y;
    const int tid = ty * 16 + tx;
    const int ox0 = blockIdx.x * 16, oy0 = blockIdx.y * 32, b = blockIdx.z;

    for (int i = tid; i < 2352; i += 256) {
        int co = i & 15, rem = i >> 4, ci = rem / 49, k = rem % 49;
        ws[i] = w[co * 147 + ci * 49 + k];
    }
    for (int i = tid; i < 2508; i += 256) {
        int ci = i / 836, rem = i - ci * 836, r = rem / 22, c = rem % 22;
        int gy = oy0 + r - 3; gy = gy < 0 ? -gy : (gy > 511 ? 1022 - gy : gy);
        int gx = ox0 + c - 3; gx = gx < 0 ? -gx : (gx > 511 ? 1022 - gx : gx);
        tile[ci * 912 + r * 24 + c] = x[((size_t)(b * 3 + ci) << 18) + (gy << 9) + gx];
    }
    __syncthreads();

    float acc[2][16];
#pragma unroll
    for (int co = 0; co < 16; co++) {
        float bv = bias[co];
        acc[0][co] = bv; acc[1][co] = bv;
    }

#pragma unroll 1
    for (int ci = 0; ci < 3; ci++) {
#pragma unroll 1
        for (int ky = 0; ky < 7; ky++) {
            const float* rp = tile + ci * 912 + (2 * ty + ky) * 24 + tx;
            const float* wp = ws + (ci * 49 + ky * 7) * 16;
#pragma unroll
            for (int kx = 0; kx < 7; kx++) {
                float x0 = rp[kx], x1 = rp[kx + 24];
                float wreg[16];
                *(float4*)(wreg)      = *(const float4*)(wp + kx * 16);
                *(float4*)(wreg + 4)  = *(const float4*)(wp + kx * 16 + 4);
                *(float4*)(wreg + 8)  = *(const float4*)(wp + kx * 16 + 8);
                *(float4*)(wreg + 12) = *(const float4*)(wp + kx * 16 + 12);
#pragma unroll
                for (int co = 0; co < 16; co++) {
                    float wv = wreg[co];
                    acc[0][co] += x0 * wv; acc[1][co] += x1 * wv;
                }
            }
        }
    }
    int oy = oy0 + 2 * ty, ox = ox0 + tx;
#pragma unroll
    for (int co = 0; co < 16; co++) {
        float* op = out + (size_t)(b * 16 + co) * 264196 + (oy + 1) * 514 + ox + 1;
        op[0] = acc[0][co]; op[514] = acc[1][co];
    }

    // fused stats partials
    int lane = tid & 31, wid = tid >> 5;
#pragma unroll
    for (int co = 0; co < 16; co++) {
        float sv = acc[0][co] + acc[1][co];
        float qv = acc[0][co] * acc[0][co] + acc[1][co] * acc[1][co];
#pragma unroll
        for (int o = 16; o > 0; o >>= 1) {
            sv += __shfl_down_sync(0xffffffffu, sv, o);
            qv += __shfl_down_sync(0xffffffffu, qv, o);
        }
        if (lane == 0) { sh_s[co * 8 + wid] = sv; sh_q[co * 8 + wid] = qv; }
    }
    __syncthreads();
    if (tid < 16) {
        float ts = 0.f, tq = 0.f;
#pragma unroll
        for (int wd = 0; wd < 8; wd++) { ts += sh_s[tid * 8 + wd]; tq += sh_q[tid * 8 + wd]; }
        atomicAdd(&s1[b * 16 + tid], (double)ts);
        atomicAdd(&s2[b * 16 + tid], (double)tq);
    }
}

// ---------------- 7x7 reflect conv 16 -> 3 + tanh; norm+relu fused; block(16,16) ----------------
__global__ __launch_bounds__(256) void k_conv_out(const float* __restrict__ in,
                                                  const float* __restrict__ w,
                                                  const float* __restrict__ bias,
                                                  float* __restrict__ out) {
    __shared__ __align__(16) float ws[3136];   // [ci16][k49][co4pad]
    __shared__ float tile[2 * 70 * 28];        // stride 28 (4*28 % 32 == 16)
    const int tx = threadIdx.x, ty = threadIdx.y;
    const int tid = ty * 16 + tx;
    const int ox0 = blockIdx.x * 16, oy0 = blockIdx.y * 64, b = blockIdx.z;

    for (int i = tid; i < 3136; i += 256) {
        int co = i & 3, rem = i >> 2, ci = rem / 49, k = rem % 49;
        ws[i] = (co < 3) ? w[co * 784 + ci * 49 + k] : 0.f;
    }

    float acc[4][3];
#pragma unroll
    for (int co = 0; co < 3; co++) {
        float bv = bias[co];
#pragma unroll
        for (int r = 0; r < 4; r++) acc[r][co] = bv;
    }

#pragma unroll 1
    for (int ci0 = 0; ci0 < 16; ci0 += 2) {
        __syncthreads();
        for (int i = tid; i < 3080; i += 256) {
            int lci = i / 1540, rem = i - lci * 1540, r = rem / 22, c = rem % 22;
            int gy = oy0 + r - 3; gy = gy < 0 ? -gy : (gy > 511 ? 1022 - gy : gy);
            int gx = ox0 + c - 3; gx = gx < 0 ? -gx : (gx > 511 ? 1022 - gx : gx);
            int bc = b * 16 + ci0 + lci;
            float v = in[(size_t)bc * 264196 + (gy + 1) * 514 + gx + 1];
            tile[lci * 1960 + r * 28 + c] = fmaxf(0.f, (v - g_mean[bc]) * g_rstd[bc]);
        }
        __syncthreads();
#pragma unroll 1
        for (int lci = 0; lci < 2; lci++) {
            int ci = ci0 + lci;
#pragma unroll 1
            for (int ky = 0; ky < 7; ky++) {
                const float* rp = tile + lci * 1960 + (4 * ty + ky) * 28 + tx;
                const float* wp = ws + (ci * 49 + ky * 7) * 4;
#pragma unroll
                for (int kx = 0; kx < 7; kx++) {
                    float4 wv = *(const float4*)(wp + kx * 4);
#pragma unroll
                    for (int r = 0; r < 4; r++) {
                        float xv = rp[kx + r * 28];
                        acc[r][0] += xv * wv.x; acc[r][1] += xv * wv.y; acc[r][2] += xv * wv.z;
                    }
                }
            }
        }
    }
    int ox = ox0 + tx;
#pragma unroll
    for (int r = 0; r < 4; r++) {
        int oy = oy0 + 4 * ty + r;
#pragma unroll
        for (int co = 0; co < 3; co++)
            out[((size_t)(b * 3 + co) << 18) + (oy << 9) + ox] = tanhf(acc[r][co]);
    }
}

// ---------------- 3x3 stride-2 conv; norm+relu fused; block(32,8), 4 rows x 8 cout + stats ----------------
// out tile 32x32; dynamic smem: tile[4*65*68] + ws[288] + sh_s[64] + sh_q[64]
__global__ __launch_bounds__(256) void k_down(const float* __restrict__ in,
                                              const float* __restrict__ w,
                                              const float* __restrict__ bias,
                                              float* __restrict__ out,
                                              int Cin, int Cout, int Hin,
                                              double* __restrict__ s1,
                                              double* __restrict__ s2) {
    const int Wp = Hin + 2, PPin = Wp * Wp;
    const int Hout = Hin >> 1, Wop = Hout + 2, PPout = Wop * Wop;
    const int groups = Cout >> 3;
    const int b = blockIdx.z / groups, cog = (blockIdx.z % groups) * 8;
    const int ox0 = blockIdx.x * 32, oy0 = blockIdx.y * 32;
    extern __shared__ __align__(16) float dsm[];
    float* tile = dsm;            // 4 * 65 * 68 = 17680 floats; E cols 0..32, O at +34
    float* ws   = dsm + 17680;    // [lci4][k9][co8] = 288
    float* sh_s = dsm + 17968;    // 64
    float* sh_q = dsm + 18032;    // 64
    const int tx = threadIdx.x, ty = threadIdx.y;
    const int tid = ty * 32 + tx;
    const int ybase = 2 * oy0, xbase = 2 * ox0;

    float acc[4][8];
#pragma unroll
    for (int co = 0; co < 8; co++) {
        float bv = bias[cog + co];
#pragma unroll
        for (int r = 0; r < 4; r++) acc[r][co] = bv;
    }

    for (int ci0 = 0; ci0 < Cin; ci0 += 4) {
        __syncthreads();
        for (int i = tid; i < 288; i += 256) {
            int co = i & 7, rem = i >> 3, lci = rem / 9, k = rem % 9;
            ws[i] = w[((size_t)(cog + co) * Cin + ci0 + lci) * 9 + k];
        }
        const int bcb = b * Cin + ci0;
#pragma unroll 1
        for (int lci = 0; lci < 4; lci++) {
            float m = g_mean[bcb + lci], rs = g_rstd[bcb + lci];
            const float* ip = in + (size_t)(bcb + lci) * PPin + (size_t)ybase * Wp + xbase;
            float* tp = tile + lci * 4420;
#pragma unroll 1
            for (int r = ty; r < 65; r += 8) {
                float2 v = *(const float2*)(ip + r * Wp + 2 * tx);
                tp[r * 68 + tx]      = fmaxf(0.f, (v.x - m) * rs);
                tp[r * 68 + 34 + tx] = fmaxf(0.f, (v.y - m) * rs);
            }
            if (tid < 65) {   // input cols 64,65 -> E col 32, O col 32
                float2 v = *(const float2*)(ip + tid * Wp + 64);
                tp[tid * 68 + 32] = fmaxf(0.f, (v.x - m) * rs);
                tp[tid * 68 + 66] = fmaxf(0.f, (v.y - m) * rs);
            }
        }
        __syncthreads();
#pragma unroll 1
        for (int lci = 0; lci < 4; lci++) {
            const float* tl = tile + lci * 4420 + (8 * ty) * 68;
            const float* wl = ws + lci * 72;
#pragma unroll
            for (int ky = 0; ky < 3; ky++) {
#pragma unroll
                for (int kx = 0; kx < 3; kx++) {
                    int off = ky * 68 + (kx & 1) * 34 + tx + (kx >> 1);
                    float x0 = tl[off], x1 = tl[off + 136], x2 = tl[off + 272], x3 = tl[off + 408];
                    float wreg[8];
                    *(float4*)(wreg)     = *(const float4*)(wl + (ky * 3 + kx) * 8);
                    *(float4*)(wreg + 4) = *(const float4*)(wl + (ky * 3 + kx) * 8 + 4);
#pragma unroll
                    for (int co = 0; co < 8; co++) {
                        float wv = wreg[co];
                        acc[0][co] += x0 * wv; acc[1][co] += x1 * wv;
                        acc[2][co] += x2 * wv; acc[3][co] += x3 * wv;
                    }
                }
            }
        }
    }
    int oy = oy0 + 4 * ty, ox = ox0 + tx;
#pragma unroll
    for (int co = 0; co < 8; co++) {
        float* op = out + (size_t)(b * Cout + cog + co) * PPout + (oy + 1) * Wop + ox + 1;
        op[0] = acc[0][co]; op[Wop] = acc[1][co];
        op[2 * Wop] = acc[2][co]; op[3 * Wop] = acc[3][co];
    }

    // fused stats partials
    int lane = tid & 31, wid = tid >> 5;
#pragma unroll
    for (int co = 0; co < 8; co++) {
        float sv = (acc[0][co] + acc[1][co]) + (acc[2][co] + acc[3][co]);
        float qv = (acc[0][co] * acc[0][co] + acc[1][co] * acc[1][co]) +
                   (acc[2][co] * acc[2][co] + acc[3][co] * acc[3][co]);
#pragma unroll
        for (int o = 16; o > 0; o >>= 1) {
            sv += __shfl_down_sync(0xffffffffu, sv, o);
            qv += __shfl_down_sync(0xffffffffu, qv, o);
        }
        if (lane == 0) { sh_s[co * 8 + wid] = sv; sh_q[co * 8 + wid] = qv; }
    }
    __syncthreads();
    if (tid < 8) {
        float ts = 0.f, tq = 0.f;
#pragma unroll
        for (int wd = 0; wd < 8; wd++) { ts += sh_s[tid * 8 + wd]; tq += sh_q[tid * 8 + wd]; }
        atomicAdd(&s1[b * Cout + cog + tid], (double)ts);
        atomicAdd(&s2[b * Cout + cog + tid], (double)tq);
    }
}

// ---------------- transposed 3x3 s2 p1 op1; norm+relu fused; block(32,8), 1 quad/thread + stats ----------------
__global__ __launch_bounds__(256) void k_up(const float* __restrict__ in,
                                            const float* __restrict__ w,
                                            const float* __restrict__ bias,
                                            float* __restrict__ out,
                                            int Cin, int Cout, int Hin,
                                            double* __restrict__ s1,
                                            double* __restrict__ s2) {
    const int Wp = Hin + 2, PPin = Wp * Wp;
    const int Hout = Hin * 2, Wop = Hout + 2, PPout = Wop * Wop;
    const int groups = Cout >> 3;
    const int b = blockIdx.z / groups, cog = (blockIdx.z % groups) * 8;
    const int ox0 = blockIdx.x * 64, oy0 = blockIdx.y * 16;
    const int iy0 = oy0 >> 1, ix0 = ox0 >> 1;
    __shared__ float tile[4 * 9 * 33];             // 9 rows x 33 cols per lci
    __shared__ __align__(16) float ws[4 * 8 * 12]; // [lci][co][12pad]
    __shared__ float sh_s[64], sh_q[64];
    const int tx = threadIdx.x, ty = threadIdx.y;
    const int tid = ty * 32 + tx;

    float acc[4][8];
#pragma unroll
    for (int co = 0; co < 8; co++) {
        float bv = bias[cog + co];
#pragma unroll
        for (int p = 0; p < 4; p++) acc[p][co] = bv;
    }

    for (int ci0 = 0; ci0 < Cin; ci0 += 4) {
        __syncthreads();
        for (int i = tid; i < 288; i += 256) {
            int lci = i / 72, rem = i - lci * 72, co = rem / 9, k = rem % 9;
            ws[lci * 96 + co * 12 + k] = w[((size_t)(ci0 + lci) * Cout + cog + co) * 9 + k];
        }
        const int bcb = b * Cin + ci0;
        for (int i = tid; i < 1188; i += 256) {
            int lci = i / 297, rem = i - lci * 297, r = rem / 33, c = rem - r * 33;
            int bc = bcb + lci;
            float v = in[(size_t)bc * PPin + (size_t)(iy0 + r + 1) * Wp + ix0 + c + 1];
            tile[lci * 297 + r * 33 + c] = fmaxf(0.f, (v - g_mean[bc]) * g_rstd[bc]);
        }
        __syncthreads();
#pragma unroll 1
        for (int lci = 0; lci < 4; lci++) {
            const float* tp = tile + lci * 297 + ty * 33 + tx;
            float v00 = tp[0],  v01 = tp[1];
            float v10 = tp[33], v11 = tp[34];
            const float* wl = ws + lci * 96;
#pragma unroll
            for (int co = 0; co < 8; co++) {
                float4 wa = *(const float4*)(wl + co * 12);     // w0 w1 w2 w3
                float4 wb = *(const float4*)(wl + co * 12 + 4); // w4 w5 w6 w7
                float w8 = wl[co * 12 + 8];
                acc[0][co] += v00 * wb.x;                                   // (2r,2c)
                acc[1][co] += v01 * wa.w + v00 * wb.y;                      // (2r,2c+1)
                acc[2][co] += v10 * wa.y + v00 * wb.w;                      // (2r+1,2c)
                acc[3][co] += v11 * wa.x + v10 * wa.z + v01 * wb.z + v00 * w8;
            }
        }
    }
#pragma unroll
    for (int p = 0; p < 4; p++) {
        int py = p >> 1, px = p & 1;
        int oy = oy0 + 2 * ty + py, ox = ox0 + 2 * tx + px;
#pragma unroll
        for (int co = 0; co < 8; co++)
            out[(size_t)(b * Cout + cog + co) * PPout + (oy + 1) * Wop + ox + 1] = acc[p][co];
    }

    // fused stats partials
    int lane = tid & 31, wid = tid >> 5;
#pragma unroll
    for (int co = 0; co < 8; co++) {
        float sv = (acc[0][co] + acc[1][co]) + (acc[2][co] + acc[3][co]);
        float qv = (acc[0][co] * acc[0][co] + acc[1][co] * acc[1][co]) +
                   (acc[2][co] * acc[2][co] + acc[3][co] * acc[3][co]);
#pragma unroll
        for (int o = 16; o > 0; o >>= 1) {
            sv += __shfl_down_sync(0xffffffffu, sv, o);
            qv += __shfl_down_sync(0xffffffffu, qv, o);
        }
        if (lane == 0) { sh_s[co * 8 + wid] = sv; sh_q[co * 8 + wid] = qv; }
    }
    __syncthreads();
    if (tid < 8) {
        float ts = 0.f, tq = 0.f;
#pragma unroll
        for (int wd = 0; wd < 8; wd++) { ts += sh_s[tid * 8 + wd]; tq += sh_q[tid * 8 + wd]; }
        atomicAdd(&s1[b * Cout + cog + tid], (double)ts);
        atomicAdd(&s2[b * Cout + cog + tid], (double)tq);
    }
}

// ---------------- finalize: mean/rstd from accumulators, fill halo, zero accumulators ----------------
__global__ void k_finalize(double* __restrict__ s1, double* __restrict__ s2,
                           float* __restrict__ base, int W, int HW, int do_halo) {
    int bc = blockIdx.x;
    __shared__ float smv;
    if (threadIdx.x == 0) {
        double m = s1[bc] / HW;
        double var = s2[bc] / HW - m * m;
        if (var < 0.0) var = 0.0;
        g_mean[bc] = (float)m;
        g_rstd[bc] = rsqrtf((float)var + 1e-5f);
        s1[bc] = 0.0; s2[bc] = 0.0;   // ready for next graph replay
        smv = (float)m;
    }
    __syncthreads();
    if (do_halo) {
        float m = smv;
        int Wp = W + 2;
        float* p = base + (size_t)bc * Wp * Wp;
        for (int i = threadIdx.x; i < Wp; i += 256) {
            p[i] = m;
            p[(size_t)(Wp - 1) * Wp + i] = m;
            p[(size_t)i * Wp] = m;
            p[(size_t)i * Wp + Wp - 1] = m;
        }
    }
}

// ---------------- per-instance mean pooling ----------------
__global__ void k_pool_zero() {
    int i = threadIdx.x;
    g_pcnt[i] = 0.f;
    g_psum[i] = 0.f; g_psum[i + 256] = 0.f; g_psum[i + 512] = 0.f;
}

__global__ void k_pool_accum(const float* __restrict__ feat, const int* __restrict__ ids) {
    __shared__ float ss[96];
    __shared__ float sc[32];
    int tid = threadIdx.x;
    if (tid < 96) ss[tid] = 0.f;
    if (tid < 32) sc[tid] = 0.f;
    __syncthreads();
    int b = blockIdx.y;
    const int HW = 262144;
    const float* f0 = feat + (size_t)b * 3 * HW;
    const int* idp = ids + (size_t)b * HW;
    for (int i = blockIdx.x * blockDim.x + tid; i < HW; i += gridDim.x * blockDim.x) {
        int id = idp[i];
        atomicAdd(&ss[id * 3 + 0], f0[i]);
        atomicAdd(&ss[id * 3 + 1], f0[i + HW]);
        atomicAdd(&ss[id * 3 + 2], f0[i + 2 * HW]);
        atomicAdd(&sc[id], 1.f);
    }
    __syncthreads();
    if (tid < 96) atomicAdd(&g_psum[b * 96 + tid], ss[tid]);
    if (tid < 32) atomicAdd(&g_pcnt[b * 32 + tid], sc[tid]);
}

__global__ void k_pool_mean() {
    int i = threadIdx.x;
    float c = g_pcnt[i];
    c = c > 0.f ? c : 1.f;
    g_psum[i * 3 + 0] /= c; g_psum[i * 3 + 1] /= c; g_psum[i * 3 + 2] /= c;
}

__global__ void k_pool_scatter(const int* __restrict__ ids, float* __restrict__ out) {
    const int HW = 262144;
    int total = 8 * HW;
    for (int i = blockIdx.x * blockDim.x + threadIdx.x; i < total; i += gridDim.x * blockDim.x) {
        int b = i >> 18, p = i & (HW - 1);
        int id = ids[i];
        const float* m = &g_psum[(b * 32 + id) * 3];
        out[((size_t)(b * 3 + 0) << 18) + p] = m[0];
        out[((size_t)(b * 3 + 1) << 18) + p] = m[1];
        out[((size_t)(b * 3 + 2) << 18) + p] = m[2];
    }
}

// ---------------- host ----------------
extern "C" void kernel_launch(void* const* d_in, const int* in_sizes, int n_in,
                              void* d_out, int out_size) {
    const float* x     = (const float*)d_in[0];
    const int*   imap  = (const int*)  d_in[1];
    const float* w_in  = (const float*)d_in[2];
    const float* b_in  = (const float*)d_in[3];
    const float* wd[4], *bd[4], *wu[4], *bu[4];
    for (int i = 0; i < 4; i++) {
        wd[i] = (const float*)d_in[4 + 2 * i];
        bd[i] = (const float*)d_in[5 + 2 * i];
        wu[i] = (const float*)d_in[12 + 2 * i];
        bu[i] = (const float*)d_in[13 + 2 * i];
    }
    const float* w_out = (const float*)d_in[20];
    const float* b_out = (const float*)d_in[21];

    static const size_t OFF[10] = {
        0u, 33817088u, 50857472u, 59510272u, 63970816u, 66338304u,
        70798848u, 79451648u, 96492032u, 130309120u
    };
    // per-layer stat-accumulator offsets: 8 * cumsum(channels 16,32,64,128,256,128,64,32,16)
    static const int SOFF[9] = {0, 128, 384, 896, 1920, 3968, 4992, 5504, 5760};
    const int DSMEM = 18096 * 4;   // k_down dynamic smem bytes

    float* act;
    double *s1, *s2;
    cudaGetSymbolAddress((void**)&act, g_act);
    cudaGetSymbolAddress((void**)&s1, g_s1);
    cudaGetSymbolAddress((void**)&s2, g_s2);
    float* outp = (float*)d_out;

    cudaFuncSetAttribute(k_down, cudaFuncAttributeMaxDynamicSharedMemorySize, DSMEM);

    // input conv -> L0 (raw) + fused stats; finalize computes mean/rstd + halo
    k_conv_in<<<dim3(32, 16, 8), dim3(16, 16)>>>(x, w_in, b_in, act + OFF[0],
                                                 s1 + SOFF[0], s2 + SOFF[0]);
    k_finalize<<<8 * 16, 256>>>(s1 + SOFF[0], s2 + SOFF[0], act + OFF[0], 512, 262144, 1);

    int C = 16, H = 512;
    // down path
    for (int i = 0; i < 4; i++) {
        int Cout = 2 * C, Hout = H / 2;
        dim3 g(Hout / 32, Hout / 32, 8 * (Cout / 8));
        k_down<<<g, dim3(32, 8), DSMEM>>>(act + OFF[i], wd[i], bd[i], act + OFF[i + 1],
                                          C, Cout, H, s1 + SOFF[i + 1], s2 + SOFF[i + 1]);
        k_finalize<<<8 * Cout, 256>>>(s1 + SOFF[i + 1], s2 + SOFF[i + 1],
                                      act + OFF[i + 1], Hout, Hout * Hout, 1);
        C = Cout; H = Hout;
    }

    // up path
    for (int i = 0; i < 4; i++) {
        int Cout = C / 2, Hout = 2 * H;
        dim3 g(Hout / 64, Hout / 16, 8 * (Cout / 8));
        k_up<<<g, dim3(32, 8)>>>(act + OFF[4 + i], wu[i], bu[i], act + OFF[5 + i], C, Cout, H,
                                 s1 + SOFF[5 + i], s2 + SOFF[5 + i]);
        k_finalize<<<8 * Cout, 256>>>(s1 + SOFF[5 + i], s2 + SOFF[5 + i],
                                      act + OFF[5 + i], Hout, Hout * Hout, i < 3 ? 1 : 0);
        C = Cout; H = Hout;
    }

    // output conv + tanh (norm+relu fused): L8 -> L9 (unpadded)
    k_conv_out<<<dim3(32, 8, 8), dim3(16, 16)>>>(act + OFF[8], w_out, b_out, act + OFF[9]);

    // instance-mean pooling -> d_out
    k_pool_zero<<<1, 256>>>();
    k_pool_accum<<<dim3(64, 8), 256>>>(act + OFF[9], imap);
    k_pool_mean<<<1, 256>>>();
    k_pool_scatter<<<8192, 256>>>(imap, outp);
}